// round 4
// baseline (speedup 1.0000x reference)
#include <cuda_runtime.h>

// ExponentialUnitNorm, fused single-pass blocked scan, smem-resident tile.
// s_t = 0.01*|x_t| + 0.99*s_{t-1};  out = x * rsqrt(s).
// B=16, C=1, T=2000, F=481.
//
// 3200 blocks of 256 threads: chain = (b, f-half), seg = time segment.
//   chain = vb % 32 (b*2+half), seg = vb / 32  -> seg-major scheduling,
//   within-chain seg order increases with ticket => deadlock-free lookback.
// Phase 1: load L=20 steps, stash tile in smem, compute zero-init local scan.
// Publish 256-wide partial + flag. Phase 2: wait on earlier same-chain flags,
// rebuild s_start via s = P_k + 0.99^L * s. Phase 3: replay from smem, store.
// Global traffic: 123 MB read (once) + 123 MB write.

#define TT 2000
#define FF 481
#define BB 16
#define SS 100
#define LL 20
#define NTHR 256
#define NCH  (BB * 2)          // 32 chains
#define NBLK (NCH * SS)        // 3200

#define ALPHA_F 0.99f
#define OMA_F   0.00999999977648258209228515625f  // (float)(1.0 - 0.99)
#define EPSF    1e-14f
#define AL_SEG  0.81790693f                       // 0.99^20

__device__ float        g_partial[NBLK * NTHR];
__device__ int          g_flag[NBLK];
__device__ unsigned int g_ticket;

__global__ void eun_reset() {
    int i = blockIdx.x * blockDim.x + threadIdx.x;
    if (i < NBLK) g_flag[i] = 0;
    if (i == 0) g_ticket = 0u;
}

__device__ __forceinline__ float mag_of(float2 v) {
    float m = fmaxf(fmaf(v.y, v.y, v.x * v.x), EPSF);
    return m * __frsqrt_rn(m);          // sqrt(m)
}

__global__ __launch_bounds__(NTHR, 4)
void eun_fused(const float2* __restrict__ x, const float* __restrict__ init,
               float2* __restrict__ out) {
    __shared__ float2 tile[LL][NTHR];   // 40 KB
    __shared__ unsigned int s_vb;

    const int tid = threadIdx.x;
    if (tid == 0) s_vb = atomicAdd(&g_ticket, 1u);
    __syncthreads();
    const int vb    = (int)s_vb;
    const int chain = vb & (NCH - 1);   // b*2 + half
    const int seg   = vb / NCH;
    const int b     = chain >> 1;
    const int half  = chain & 1;

    const int flane = half * NTHR + tid;
    const bool valid = flane < FF;
    const int fidx = valid ? flane : (FF - 1);  // clamp: duplicate last chain

    const int base = (b * TT + seg * LL) * FF + fidx;
    const float2* px = x + base;

    // ---- phase 1: load tile, local zero-init scan ----
    float s = 0.0f;
    #pragma unroll
    for (int j = 0; j < LL; j++) {
        float2 v = __ldcs(px + j * FF);
        tile[j][tid] = v;
        s = fmaf(OMA_F, mag_of(v), ALPHA_F * s);
    }

    // ---- publish partial + flag ----
    g_partial[vb * NTHR + tid] = s;
    __threadfence();
    __syncthreads();
    if (tid == 0) atomicExch(&g_flag[vb], 1);

    // ---- phase 2: reconstruct segment-start state ----
    float st = __ldg(init + fidx);
    if (seg > 0) {
        const int cb = chain * SS * 0 + 0;  // flags/partials are vb-indexed
        // chain's seg k lives at vb_k = k*NCH + chain
        for (;;) {
            int ok = 1;
            if (tid < seg) ok = __ldcg(&g_flag[tid * NCH + chain]);
            if (__syncthreads_and(ok)) break;
            __nanosleep(100);
        }
        (void)cb;
        const float* pp = g_partial + (size_t)chain * NTHR + tid; // + k*NCH*NTHR
        const int STRD = NCH * NTHR;
        int k = 0;
        #pragma unroll 1
        for (; k + 8 <= seg; k += 8) {
            float p0 = __ldcg(pp + (k + 0) * STRD);
            float p1 = __ldcg(pp + (k + 1) * STRD);
            float p2 = __ldcg(pp + (k + 2) * STRD);
            float p3 = __ldcg(pp + (k + 3) * STRD);
            float p4 = __ldcg(pp + (k + 4) * STRD);
            float p5 = __ldcg(pp + (k + 5) * STRD);
            float p6 = __ldcg(pp + (k + 6) * STRD);
            float p7 = __ldcg(pp + (k + 7) * STRD);
            st = fmaf(AL_SEG, st, p0); st = fmaf(AL_SEG, st, p1);
            st = fmaf(AL_SEG, st, p2); st = fmaf(AL_SEG, st, p3);
            st = fmaf(AL_SEG, st, p4); st = fmaf(AL_SEG, st, p5);
            st = fmaf(AL_SEG, st, p6); st = fmaf(AL_SEG, st, p7);
        }
        for (; k < seg; k++)
            st = fmaf(AL_SEG, st, __ldcg(pp + k * STRD));
    }

    // ---- phase 3: replay tile from smem, emit output ----
    float2* po = out + base;
    #pragma unroll
    for (int j = 0; j < LL; j++) {
        float2 v = tile[j][tid];
        st = fmaf(OMA_F, mag_of(v), ALPHA_F * st);
        float r = __frsqrt_rn(st);
        float2 o; o.x = v.x * r; o.y = v.y * r;
        if (valid) __stcs(po + j * FF, o);
    }
}

extern "C" void kernel_launch(void* const* d_in, const int* in_sizes, int n_in,
                              void* d_out, int out_size) {
    const float2* x = (const float2*)d_in[0];   // [16,1,2000,481,2] f32
    const float* init = (const float*)d_in[1];  // [481] f32
    float2* out = (float2*)d_out;

    eun_reset<<<4, 1024>>>();
    eun_fused<<<NBLK, NTHR>>>(x, init, out);
}